// round 13
// baseline (speedup 1.0000x reference)
#include <cuda_runtime.h>
#include <math.h>
#include <stdint.h>

#define NG 1000

// x as pre-swizzled bf16 hi/lo slot image: 4 slots x (hi 8K | lo 8K)
__device__ __align__(16) char g_ximg[65536];
// h1 as pre-swizzled slot image per gene: 16 slots x 16KB
__device__ __align__(16) char g_h1img[(size_t)NG * 262144];
__device__ float g_part[(size_t)NG * 4 * 128];

// k1 smem: b1s@0(1K) | A@1024 2x16K | B@33792 2x16K | WF@66560 2x16K = 99328
#define K1_A  1024
#define K1_B  33792
#define K1_WF 66560
#define SM1_BYTES 99328
// k2 smem: b2s@0 w3s@512 red@1024(3K) | A@4096 2x16K | B@36864 2x16K | WF@69632 2x16K = 102400
#define K2_A  4096
#define K2_B  36864
#define K2_WF 69632
#define SM2_BYTES 102400

__device__ __forceinline__ uint32_t smem_u32(const void* p){
    uint32_t a;
    asm("{ .reg .u64 t; cvta.to.shared.u64 t, %1; cvt.u32.u64 %0, t; }" : "=r"(a) : "l"(p));
    return a;
}
__device__ __forceinline__ uint32_t sw64(uint32_t x){ return x ^ ((x >> 3) & 0x30u); }

__device__ __forceinline__ void split2(float f0, float f1, uint32_t& hp, uint32_t& lp){
    asm("cvt.rn.bf16x2.f32 %0, %1, %2;" : "=r"(hp) : "f"(f1), "f"(f0));
    float h1f = __uint_as_float(hp & 0xFFFF0000u);
    float h0f = __uint_as_float(hp << 16);
    asm("cvt.rn.bf16x2.f32 %0, %1, %2;" : "=r"(lp) : "f"(f1 - h1f), "f"(f0 - h0f));
}
__device__ __forceinline__ float gelu(float v){
    return 0.5f * v * (1.0f + erff(v * 0.70710678118654752440f));
}
__device__ __forceinline__ void ldsm4(uint32_t* r, uint32_t a){
    asm volatile("ldmatrix.sync.aligned.m8n8.x4.shared.b16 {%0,%1,%2,%3}, [%4];"
      : "=r"(r[0]), "=r"(r[1]), "=r"(r[2]), "=r"(r[3]) : "r"(a));
}
__device__ __forceinline__ void mmabf(float* c, const uint32_t* a, uint32_t b0, uint32_t b1){
    asm volatile("mma.sync.aligned.m16n8k16.row.col.f32.bf16.bf16.f32 "
      "{%0,%1,%2,%3},{%4,%5,%6,%7},{%8,%9},{%0,%1,%2,%3};"
      : "+f"(c[0]), "+f"(c[1]), "+f"(c[2]), "+f"(c[3])
      : "r"(a[0]), "r"(a[1]), "r"(a[2]), "r"(a[3]), "r"(b0), "r"(b1));
}
#define CP16(d,s)  asm volatile("cp.async.cg.shared.global [%0], [%1], 16;" :: "r"(d), "l"(s) : "memory")
#define CPCOMMIT() asm volatile("cp.async.commit_group;" ::: "memory")
#define CPWAIT0()  asm volatile("cp.async.wait_group 0;" ::: "memory")

struct Frag { uint32_t offA, mA, offB, mB, ksel; };

// warp grid 2(wm) x 2(wn); warp tile 64M x 64N
__device__ __forceinline__ Frag mk_frag(int lane, int wm, int wn){
    Frag f;
    uint32_t rA = wm * 64 + (lane & 7) + ((lane >> 3) & 1) * 8;
    uint32_t rB = wn * 64 + (lane & 7) + ((lane >> 3) & 1) * 8;
    f.ksel = ((lane >> 4) & 1) * 16;
    f.mA = ((rA >> 1) & 3) << 4;  f.mB = ((rB >> 1) & 3) << 4;
    f.offA = rA * 64;             f.offB = rB * 64;
    return f;
}

// one K=32 tile, 64B rows. A: aB hi, aB+8192 lo; B: bB hi, bB+8192 lo.
// Warp tile 64x64: c[i<4][jt<8][4]. Split-term outermost (no acc RAW stalls).
__device__ __forceinline__ void mma32(uint32_t aB, uint32_t bB, const Frag& f, float c[4][8][4])
{
#pragma unroll
    for (int ks = 0; ks < 2; ks++){
        uint32_t ka = ks * 32 + f.ksel;
        uint32_t ao = f.offA + (ka ^ f.mA);
        uint32_t bo = f.offB + (ka ^ f.mB);
        uint32_t ah[4][4], al[4][4], bh[4][4], bl[4][4];
#pragma unroll
        for (int i = 0; i < 4; i++){ ldsm4(ah[i], aB + ao + i*1024u); ldsm4(al[i], aB + 8192u + ao + i*1024u); }
#pragma unroll
        for (int j = 0; j < 4; j++){ ldsm4(bh[j], bB + bo + j*1024u); ldsm4(bl[j], bB + 8192u + bo + j*1024u); }
        // term 1: Ah*Bh
#pragma unroll
        for (int i = 0; i < 4; i++)
#pragma unroll
        for (int jt = 0; jt < 8; jt++){
            int j = jt >> 1, s2 = jt & 1;
            mmabf(c[i][jt], ah[i], bh[j][s2], bh[j][s2+2]);
        }
        // term 2: Ah*Bl
#pragma unroll
        for (int i = 0; i < 4; i++)
#pragma unroll
        for (int jt = 0; jt < 8; jt++){
            int j = jt >> 1, s2 = jt & 1;
            mmabf(c[i][jt], ah[i], bl[j][s2], bl[j][s2+2]);
        }
        // term 3: Al*Bh
#pragma unroll
        for (int i = 0; i < 4; i++)
#pragma unroll
        for (int jt = 0; jt < 8; jt++){
            int j = jt >> 1, s2 = jt & 1;
            mmabf(c[i][jt], al[i], bh[j][s2], bh[j][s2+2]);
        }
    }
}

// convert one W fp32 tile (smem [32k][128n], 512B rows) -> bf16 hi/lo planes.
// 128 threads: thread nB handles its column for all 32 k.
__device__ __forceinline__ void convW(const float* wf, char* bB, int nB){
    char* Bh = bB; char* Bl = bB + 8192;
#pragma unroll
    for (int l = 0; l < 32; l += 4){
        float f0 = wf[(l+0) * 128 + nB], f1 = wf[(l+1) * 128 + nB];
        float f2 = wf[(l+2) * 128 + nB], f3 = wf[(l+3) * 128 + nB];
        uint32_t hp0, lp0, hp1, lp1;
        split2(f0, f1, hp0, lp0);
        split2(f2, f3, hp1, lp1);
        uint32_t off = sw64((uint32_t)nB * 64 + l * 2);
        *(uint2*)(Bh + off) = make_uint2(hp0, hp1);
        *(uint2*)(Bl + off) = make_uint2(lp0, lp1);
    }
}

// ============ k0: x -> pre-swizzled bf16 hi/lo image (once) ============
__global__ void k0(const float* __restrict__ x)
{
    int tid = threadIdx.x;           // 256
    int m = tid >> 1, h = tid & 1;
    const float4* xr = (const float4*)(x + m * 128 + h * 64);
#pragma unroll
    for (int j4 = 0; j4 < 16; j4++){
        float4 v = xr[j4];
        int l = j4 * 4;
        int slot = h * 2 + (l >> 5);
        int kk = l & 31;
        uint32_t hp0, lp0, hp1, lp1;
        split2(v.x, v.y, hp0, lp0);
        split2(v.z, v.w, hp1, lp1);
        uint32_t off = sw64((uint32_t)m * 64 + kk * 2);
        *(uint2*)(g_ximg + slot * 16384 + off) = make_uint2(hp0, hp1);
        *(uint2*)(g_ximg + slot * 16384 + 8192 + off) = make_uint2(lp0, lp1);
    }
}

// ============ k1: h1 = gelu(x @ W1 + b1) -> h1 slot image ============
// grid (4, 1000). 128 threads (4 warps, 2x2), 2 CTAs/SM. 4 K32 tiles.
__global__ void __launch_bounds__(128, 2)
k1(const float* __restrict__ W1, const float* __restrict__ b1)
{
    extern __shared__ char sm[];
    uint32_t sb = smem_u32(sm);
    const int nc = blockIdx.x, g = blockIdx.y;
    const int tid = threadIdx.x, lane = tid & 31, w = tid >> 5;
    const int wm = w & 1, wn = w >> 1;

    const float* Wg = W1 + (size_t)g * 65536 + nc * 128;

    auto cpA = [&](int kt, int s){
        const char* src = g_ximg + (size_t)kt * 16384;
        uint32_t dst = sb + K1_A + s * 16384;
#pragma unroll
        for (int i = 0; i < 8; i++){
            uint32_t idx = tid + i * 128;
            CP16(dst + idx * 16, src + idx * 16);
        }
    };
    auto cpW = [&](int kt, int s){
        uint32_t dst = sb + K1_WF + s * 16384;
        const float* src = Wg + (size_t)kt * 32 * 512;
#pragma unroll
        for (int i = 0; i < 8; i++){
            uint32_t idx = tid + i * 128, k = idx >> 5, n4 = idx & 31;
            CP16(dst + k * 512 + n4 * 16, src + (size_t)k * 512 + n4 * 4);
        }
    };

    // prologue: A0, W0, W1 in one group
    cpA(0, 0); cpW(0, 0); cpW(1, 1); CPCOMMIT();
    float* b1s = (float*)sm;
    b1s[tid] = b1[(size_t)g * 512 + nc * 128 + tid];
    CPWAIT0();
    __syncthreads();
    convW((const float*)(sm + K1_WF), sm + K1_B, tid);   // B0
    __syncthreads();

    float c[4][8][4];
#pragma unroll
    for (int i = 0; i < 4; i++)
#pragma unroll
    for (int jt = 0; jt < 8; jt++)
#pragma unroll
    for (int q = 0; q < 4; q++) c[i][jt][q] = 0.0f;
    Frag f = mk_frag(lane, wm, wn);

#pragma unroll
    for (int kt = 0; kt < 4; kt++){
        if (kt + 1 < 4){ cpA(kt + 1, (kt + 1) & 1); CPCOMMIT(); }
        if (kt + 2 < 4){ cpW(kt + 2, kt & 1); CPCOMMIT(); }
        if (kt + 1 < 4)
            convW((const float*)(sm + K1_WF + ((kt + 1) & 1) * 16384),
                  sm + K1_B + ((kt + 1) & 1) * 16384, tid);
        mma32(sb + K1_A + (kt & 1) * 16384, sb + K1_B + (kt & 1) * 16384, f, c);
        CPWAIT0();
        __syncthreads();
    }

    // epilogue: bias + gelu + split -> smem image stage (64KB @ K1_A), then coalesced copy
    char* stage = sm + K1_A;
#pragma unroll
    for (int i = 0; i < 4; i++)
#pragma unroll
    for (int jt = 0; jt < 8; jt++){
        int nl = wn * 64 + jt * 8 + 2 * (lane & 3);
        int r0 = wm * 64 + i * 16 + (lane >> 2);
        int sl = nl >> 5, kk = nl & 31;
        float bb0 = b1s[nl], bb1 = b1s[nl + 1];
        uint32_t hp, lp;
        float v0 = gelu(c[i][jt][0] + bb0);
        float v1 = gelu(c[i][jt][1] + bb1);
        split2(v0, v1, hp, lp);
        char* pp = stage + sl * 16384 + sw64((uint32_t)r0 * 64 + kk * 2);
        *(uint32_t*)pp = hp; *(uint32_t*)(pp + 8192) = lp;
        v0 = gelu(c[i][jt][2] + bb0);
        v1 = gelu(c[i][jt][3] + bb1);
        split2(v0, v1, hp, lp);
        pp = stage + sl * 16384 + sw64((uint32_t)(r0 + 8) * 64 + kk * 2);
        *(uint32_t*)pp = hp; *(uint32_t*)(pp + 8192) = lp;
    }
    __syncthreads();
    {
        char* dst = g_h1img + (size_t)g * 262144 + (size_t)nc * 65536;
#pragma unroll
        for (int i = 0; i < 32; i++){
            uint32_t idx = tid + i * 128;
            *(uint4*)(dst + idx * 16) = *(uint4*)(stage + idx * 16);
        }
    }
}

// ============ k2: partial = sum_n gelu(h1 @ W2 + b2) * W3 ============
// grid (4, 1000). 128 threads (4 warps, 2x2), 2 CTAs/SM. 16 K32 tiles.
__global__ void __launch_bounds__(128, 2)
k2(const float* __restrict__ W2, const float* __restrict__ b2, const float* __restrict__ W3)
{
    extern __shared__ char sm[];
    uint32_t sb = smem_u32(sm);
    const int nc = blockIdx.x, g = blockIdx.y;
    const int tid = threadIdx.x, lane = tid & 31, w = tid >> 5;
    const int wm = w & 1, wn = w >> 1;

    const char* h1g = g_h1img + (size_t)g * 262144;
    const float* Wg = W2 + (size_t)g * 262144 + nc * 128;

    auto cpA = [&](int kt, int s){
        const char* src = h1g + (size_t)kt * 16384;
        uint32_t dst = sb + K2_A + s * 16384;
#pragma unroll
        for (int i = 0; i < 8; i++){
            uint32_t idx = tid + i * 128;
            CP16(dst + idx * 16, src + idx * 16);
        }
    };
    auto cpW = [&](int kt, int s){
        uint32_t dst = sb + K2_WF + s * 16384;
        const float* src = Wg + (size_t)kt * 32 * 512;
#pragma unroll
        for (int i = 0; i < 8; i++){
            uint32_t idx = tid + i * 128, k = idx >> 5, n4 = idx & 31;
            CP16(dst + k * 512 + n4 * 16, src + (size_t)k * 512 + n4 * 4);
        }
    };

    // prologue
    cpA(0, 0); cpW(0, 0); cpW(1, 1); CPCOMMIT();
    float* b2s = (float*)sm;
    float* w3s = (float*)(sm + 512);
    b2s[tid] = b2[(size_t)g * 512 + nc * 128 + tid];
    w3s[tid] = W3[(size_t)g * 512 + nc * 128 + tid];
    CPWAIT0();
    __syncthreads();
    convW((const float*)(sm + K2_WF), sm + K2_B, tid);   // B0
    __syncthreads();

    float c[4][8][4];
#pragma unroll
    for (int i = 0; i < 4; i++)
#pragma unroll
    for (int jt = 0; jt < 8; jt++)
#pragma unroll
    for (int q = 0; q < 4; q++) c[i][jt][q] = 0.0f;
    Frag f = mk_frag(lane, wm, wn);

    for (int kt = 0; kt < 16; kt++){
        if (kt + 1 < 16){ cpA(kt + 1, (kt + 1) & 1); CPCOMMIT(); }
        if (kt + 2 < 16){ cpW(kt + 2, kt & 1); CPCOMMIT(); }
        if (kt + 1 < 16)
            convW((const float*)(sm + K2_WF + ((kt + 1) & 1) * 16384),
                  sm + K2_B + ((kt + 1) & 1) * 16384, tid);
        mma32(sb + K2_A + (kt & 1) * 16384, sb + K2_B + (kt & 1) * 16384, f, c);
        CPWAIT0();
        __syncthreads();
    }

    // epilogue: bias + gelu + W3-dot; quad shuffle + smem reduce over 2 wn-warps
    float* red = (float*)(sm + 1024);
#pragma unroll
    for (int i = 0; i < 4; i++){
        float s0 = 0.0f, s1 = 0.0f;
#pragma unroll
        for (int jt = 0; jt < 8; jt++){
            int nl = wn * 64 + jt * 8 + 2 * (lane & 3);
            float bb0 = b2s[nl], bb1 = b2s[nl+1], ww0 = w3s[nl], ww1 = w3s[nl+1];
            s0 += gelu(c[i][jt][0] + bb0) * ww0 + gelu(c[i][jt][1] + bb1) * ww1;
            s1 += gelu(c[i][jt][2] + bb0) * ww0 + gelu(c[i][jt][3] + bb1) * ww1;
        }
        s0 += __shfl_xor_sync(0xFFFFFFFFu, s0, 1);
        s0 += __shfl_xor_sync(0xFFFFFFFFu, s0, 2);
        s1 += __shfl_xor_sync(0xFFFFFFFFu, s1, 1);
        s1 += __shfl_xor_sync(0xFFFFFFFFu, s1, 2);
        if ((lane & 3) == 0){
            int r0 = wm * 64 + i * 16 + (lane >> 2);
            red[r0 * 2 + wn] = s0;
            red[(r0 + 8) * 2 + wn] = s1;
        }
    }
    __syncthreads();
    {
        const float* rr = red + tid * 2;
        g_part[((size_t)g * 4 + nc) * 128 + tid] = rr[0] + rr[1];
    }
}

// ============ k3 ============
__global__ void k3(const float* __restrict__ b3, float* __restrict__ out)
{
    int idx = blockIdx.x * 256 + threadIdx.x;
    if (idx >= 128 * NG) return;
    int m = idx / NG;
    int g = idx - m * NG;
    const float* p = g_part + (size_t)g * 512 + m;
    out[idx] = b3[g] + ((p[0] + p[128]) + (p[256] + p[384]));
}

extern "C" void kernel_launch(void* const* d_in, const int* in_sizes, int n_in,
                              void* d_out, int out_size)
{
    const float* x  = (const float*)d_in[0];
    const float* W1 = (const float*)d_in[1];
    const float* b1 = (const float*)d_in[2];
    const float* W2 = (const float*)d_in[3];
    const float* b2 = (const float*)d_in[4];
    const float* W3 = (const float*)d_in[5];
    const float* b3 = (const float*)d_in[6];
    float* out = (float*)d_out;

    cudaFuncSetAttribute(k1, cudaFuncAttributeMaxDynamicSharedMemorySize, SM1_BYTES);
    cudaFuncSetAttribute(k2, cudaFuncAttributeMaxDynamicSharedMemorySize, SM2_BYTES);

    k0<<<1, 256>>>(x);
    dim3 grid(4, NG);
    k1<<<grid, 128, SM1_BYTES>>>(W1, b1);
    k2<<<grid, 128, SM2_BYTES>>>(W2, b2, W3);
    k3<<<(128 * NG + 255) / 256, 256>>>(b3, out);
}

// round 14
// speedup vs baseline: 1.1130x; 1.1130x over previous
#include <cuda_runtime.h>
#include <math.h>
#include <stdint.h>

#define NG 1000

// x as pre-swizzled bf16 hi/lo slot image: 4 slots x (hi 8K | lo 8K)
__device__ __align__(16) char g_ximg[65536];
// h1 as pre-swizzled slot image per gene: 16 slots x 16KB
__device__ __align__(16) char g_h1img[(size_t)NG * 262144];
__device__ float g_part[(size_t)NG * 4 * 128];

// k1 smem: b1s@0(1K) | A@1024 2x16K | B@33792 2x16K | WF@66560 2x16K = 99328
#define K1_A  1024
#define K1_B  33792
#define K1_WF 66560
#define SM1_BYTES 99328
// k2 smem: b2s@0 w3s@512 red@1024(3K) | A@4096 2x16K | B@36864 2x16K | WF@69632 2x16K = 102400
#define K2_A  4096
#define K2_B  36864
#define K2_WF 69632
#define SM2_BYTES 102400

__device__ __forceinline__ uint32_t smem_u32(const void* p){
    uint32_t a;
    asm("{ .reg .u64 t; cvta.to.shared.u64 t, %1; cvt.u32.u64 %0, t; }" : "=r"(a) : "l"(p));
    return a;
}
__device__ __forceinline__ uint32_t sw64(uint32_t x){ return x ^ ((x >> 3) & 0x30u); }

__device__ __forceinline__ void split2(float f0, float f1, uint32_t& hp, uint32_t& lp){
    asm("cvt.rn.bf16x2.f32 %0, %1, %2;" : "=r"(hp) : "f"(f1), "f"(f0));
    float h1f = __uint_as_float(hp & 0xFFFF0000u);
    float h0f = __uint_as_float(hp << 16);
    asm("cvt.rn.bf16x2.f32 %0, %1, %2;" : "=r"(lp) : "f"(f1 - h1f), "f"(f0 - h0f));
}
__device__ __forceinline__ float gelu(float v){
    return 0.5f * v * (1.0f + erff(v * 0.70710678118654752440f));
}
__device__ __forceinline__ void ldsm4(uint32_t* r, uint32_t a){
    asm volatile("ldmatrix.sync.aligned.m8n8.x4.shared.b16 {%0,%1,%2,%3}, [%4];"
      : "=r"(r[0]), "=r"(r[1]), "=r"(r[2]), "=r"(r[3]) : "r"(a));
}
__device__ __forceinline__ void mmabf(float* c, const uint32_t* a, uint32_t b0, uint32_t b1){
    asm volatile("mma.sync.aligned.m16n8k16.row.col.f32.bf16.bf16.f32 "
      "{%0,%1,%2,%3},{%4,%5,%6,%7},{%8,%9},{%0,%1,%2,%3};"
      : "+f"(c[0]), "+f"(c[1]), "+f"(c[2]), "+f"(c[3])
      : "r"(a[0]), "r"(a[1]), "r"(a[2]), "r"(a[3]), "r"(b0), "r"(b1));
}
#define CP16(d,s)  asm volatile("cp.async.cg.shared.global [%0], [%1], 16;" :: "r"(d), "l"(s) : "memory")
#define CPCOMMIT() asm volatile("cp.async.commit_group;" ::: "memory")
#define CPWAIT0()  asm volatile("cp.async.wait_group 0;" ::: "memory")

struct Frag { uint32_t offA, mA, offB, mB, ksel; };

// warp grid 2(wm) x 4(wn); warp tile 64M x 32N  (R11 proven shape)
__device__ __forceinline__ Frag mk_frag(int lane, int wm, int wn){
    Frag f;
    uint32_t rA = wm * 64 + (lane & 7) + ((lane >> 3) & 1) * 8;
    uint32_t rB = wn * 32 + (lane & 7) + ((lane >> 3) & 1) * 8;
    f.ksel = ((lane >> 4) & 1) * 16;
    f.mA = ((rA >> 1) & 3) << 4;  f.mB = ((rB >> 1) & 3) << 4;
    f.offA = rA * 64;             f.offB = rB * 64;
    return f;
}

// one K=32 tile, 64B rows. A: aB hi, aB+8192 lo; B: bB hi, bB+8192 lo.
// Split-term outermost: 16 independent MMAs between same-accumulator revisits.
__device__ __forceinline__ void mma32(uint32_t aB, uint32_t bB, const Frag& f, float c[4][4][4])
{
#pragma unroll
    for (int ks = 0; ks < 2; ks++){
        uint32_t ka = ks * 32 + f.ksel;
        uint32_t ao = f.offA + (ka ^ f.mA);
        uint32_t bo = f.offB + (ka ^ f.mB);
        uint32_t ah[4][4], al[4][4], bh[2][4], bl[2][4];
#pragma unroll
        for (int i = 0; i < 4; i++){ ldsm4(ah[i], aB + ao + i*1024u); ldsm4(al[i], aB + 8192u + ao + i*1024u); }
#pragma unroll
        for (int j = 0; j < 2; j++){ ldsm4(bh[j], bB + bo + j*1024u); ldsm4(bl[j], bB + 8192u + bo + j*1024u); }
#pragma unroll
        for (int i = 0; i < 4; i++)
#pragma unroll
        for (int jt = 0; jt < 4; jt++){
            int j = jt >> 1, s2 = jt & 1;
            mmabf(c[i][jt], ah[i], bh[j][s2], bh[j][s2+2]);
        }
#pragma unroll
        for (int i = 0; i < 4; i++)
#pragma unroll
        for (int jt = 0; jt < 4; jt++){
            int j = jt >> 1, s2 = jt & 1;
            mmabf(c[i][jt], ah[i], bl[j][s2], bl[j][s2+2]);
        }
#pragma unroll
        for (int i = 0; i < 4; i++)
#pragma unroll
        for (int jt = 0; jt < 4; jt++){
            int j = jt >> 1, s2 = jt & 1;
            mmabf(c[i][jt], al[i], bh[j][s2], bh[j][s2+2]);
        }
    }
}

// convert one W fp32 tile (smem [32k][128n], 512B rows) -> bf16 hi/lo planes.
// 256 threads: thread = (nB, khB 16-k half). Phase-rotated k order halves STS conflicts.
__device__ __forceinline__ void convW(const float* wf, char* bB, int nB, int khB, int ph){
    char* Bh = bB; char* Bl = bB + 8192;
#pragma unroll
    for (int li = 0; li < 16; li += 4){
        int l = (li + ph) & 15;            // ph in {0,8}: lane groups hit different 16B granules
        int k0 = khB * 16 + l;
        float f0 = wf[(k0+0) * 128 + nB], f1 = wf[(k0+1) * 128 + nB];
        float f2 = wf[(k0+2) * 128 + nB], f3 = wf[(k0+3) * 128 + nB];
        uint32_t hp0, lp0, hp1, lp1;
        split2(f0, f1, hp0, lp0);
        split2(f2, f3, hp1, lp1);
        uint32_t off = sw64((uint32_t)nB * 64 + (uint32_t)k0 * 2);
        *(uint2*)(Bh + off) = make_uint2(hp0, hp1);
        *(uint2*)(Bl + off) = make_uint2(lp0, lp1);
    }
}

// ============ k0: x -> pre-swizzled bf16 hi/lo image (once) ============
__global__ void k0(const float* __restrict__ x)
{
    int tid = threadIdx.x;           // 256
    int m = tid >> 1, h = tid & 1;
    const float4* xr = (const float4*)(x + m * 128 + h * 64);
#pragma unroll
    for (int j4 = 0; j4 < 16; j4++){
        float4 v = xr[j4];
        int l = j4 * 4;
        int slot = h * 2 + (l >> 5);
        int kk = l & 31;
        uint32_t hp0, lp0, hp1, lp1;
        split2(v.x, v.y, hp0, lp0);
        split2(v.z, v.w, hp1, lp1);
        uint32_t off = sw64((uint32_t)m * 64 + kk * 2);
        *(uint2*)(g_ximg + slot * 16384 + off) = make_uint2(hp0, hp1);
        *(uint2*)(g_ximg + slot * 16384 + 8192 + off) = make_uint2(lp0, lp1);
    }
}

// ============ k1: h1 = gelu(x @ W1 + b1) -> h1 slot image ============
// grid (4, 1000). 256 threads (8 warps 2x4), 2 CTAs/SM. 4 K32 tiles.
__global__ void __launch_bounds__(256, 2)
k1(const float* __restrict__ W1, const float* __restrict__ b1)
{
    extern __shared__ char sm[];
    uint32_t sb = smem_u32(sm);
    const int nc = blockIdx.x, g = blockIdx.y;
    const int tid = threadIdx.x, lane = tid & 31, w = tid >> 5;
    const int wm = w & 1, wn = w >> 1;
    const int nB = tid & 127, khB = tid >> 7;
    const int ph = ((lane >> 3) & 1) * 8;

    const float* Wg = W1 + (size_t)g * 65536 + nc * 128;

    auto cpA = [&](int kt, int s){
        const char* src = g_ximg + (size_t)kt * 16384;
        uint32_t dst = sb + K1_A + s * 16384;
#pragma unroll
        for (int i = 0; i < 4; i++){
            uint32_t idx = tid + i * 256;
            CP16(dst + idx * 16, src + idx * 16);
        }
    };
    auto cpW = [&](int kt, int s){
        uint32_t dst = sb + K1_WF + s * 16384;
        const float* src = Wg + (size_t)kt * 32 * 512;
#pragma unroll
        for (int i = 0; i < 4; i++){
            uint32_t idx = tid + i * 256, k = idx >> 5, n4 = idx & 31;
            CP16(dst + k * 512 + n4 * 16, src + (size_t)k * 512 + n4 * 4);
        }
    };

    // prologue: A0, W0, W1 in one group
    cpA(0, 0); cpW(0, 0); cpW(1, 1); CPCOMMIT();
    float* b1s = (float*)sm;
    if (tid < 128) b1s[tid] = b1[(size_t)g * 512 + nc * 128 + tid];
    CPWAIT0();
    __syncthreads();
    convW((const float*)(sm + K1_WF), sm + K1_B, nB, khB, ph);   // B0
    __syncthreads();

    float c[4][4][4];
#pragma unroll
    for (int i = 0; i < 4; i++)
#pragma unroll
    for (int jt = 0; jt < 4; jt++)
#pragma unroll
    for (int q = 0; q < 4; q++) c[i][jt][q] = 0.0f;
    Frag f = mk_frag(lane, wm, wn);

#pragma unroll
    for (int kt = 0; kt < 4; kt++){
        if (kt + 1 < 4){ cpA(kt + 1, (kt + 1) & 1); CPCOMMIT(); }
        if (kt + 2 < 4){ cpW(kt + 2, kt & 1); CPCOMMIT(); }
        // MMA first: tensor pipe starts immediately after the barrier
        mma32(sb + K1_A + (kt & 1) * 16384, sb + K1_B + (kt & 1) * 16384, f, c);
        if (kt + 1 < 4)
            convW((const float*)(sm + K1_WF + ((kt + 1) & 1) * 16384),
                  sm + K1_B + ((kt + 1) & 1) * 16384, nB, khB, ph);
        CPWAIT0();
        __syncthreads();
    }

    // epilogue: bias + gelu + split -> smem image stage (64KB @ K1_A), then coalesced copy
    char* stage = sm + K1_A;
#pragma unroll
    for (int i = 0; i < 4; i++)
#pragma unroll
    for (int jt = 0; jt < 4; jt++){
        int nl = wn * 32 + jt * 8 + 2 * (lane & 3);
        int r0 = wm * 64 + i * 16 + (lane >> 2);
        int sl = nl >> 5, kk = nl & 31;
        float bb0 = b1s[nl], bb1 = b1s[nl + 1];
        uint32_t hp, lp;
        float v0 = gelu(c[i][jt][0] + bb0);
        float v1 = gelu(c[i][jt][1] + bb1);
        split2(v0, v1, hp, lp);
        char* pp = stage + sl * 16384 + sw64((uint32_t)r0 * 64 + kk * 2);
        *(uint32_t*)pp = hp; *(uint32_t*)(pp + 8192) = lp;
        v0 = gelu(c[i][jt][2] + bb0);
        v1 = gelu(c[i][jt][3] + bb1);
        split2(v0, v1, hp, lp);
        pp = stage + sl * 16384 + sw64((uint32_t)(r0 + 8) * 64 + kk * 2);
        *(uint32_t*)pp = hp; *(uint32_t*)(pp + 8192) = lp;
    }
    __syncthreads();
    {
        char* dst = g_h1img + (size_t)g * 262144 + (size_t)nc * 65536;
#pragma unroll
        for (int i = 0; i < 16; i++){
            uint32_t idx = tid + i * 256;
            *(uint4*)(dst + idx * 16) = *(uint4*)(stage + idx * 16);
        }
    }
}

// ============ k2: partial = sum_n gelu(h1 @ W2 + b2) * W3 ============
// grid (4, 1000). 256 threads (8 warps 2x4), 2 CTAs/SM. 16 K32 tiles.
__global__ void __launch_bounds__(256, 2)
k2(const float* __restrict__ W2, const float* __restrict__ b2, const float* __restrict__ W3)
{
    extern __shared__ char sm[];
    uint32_t sb = smem_u32(sm);
    const int nc = blockIdx.x, g = blockIdx.y;
    const int tid = threadIdx.x, lane = tid & 31, w = tid >> 5;
    const int wm = w & 1, wn = w >> 1;
    const int nB = tid & 127, khB = tid >> 7;
    const int ph = ((lane >> 3) & 1) * 8;

    const char* h1g = g_h1img + (size_t)g * 262144;
    const float* Wg = W2 + (size_t)g * 262144 + nc * 128;

    auto cpA = [&](int kt, int s){
        const char* src = h1g + (size_t)kt * 16384;
        uint32_t dst = sb + K2_A + s * 16384;
#pragma unroll
        for (int i = 0; i < 4; i++){
            uint32_t idx = tid + i * 256;
            CP16(dst + idx * 16, src + idx * 16);
        }
    };
    auto cpW = [&](int kt, int s){
        uint32_t dst = sb + K2_WF + s * 16384;
        const float* src = Wg + (size_t)kt * 32 * 512;
#pragma unroll
        for (int i = 0; i < 4; i++){
            uint32_t idx = tid + i * 256, k = idx >> 5, n4 = idx & 31;
            CP16(dst + k * 512 + n4 * 16, src + (size_t)k * 512 + n4 * 4);
        }
    };

    // prologue
    cpA(0, 0); cpW(0, 0); cpW(1, 1); CPCOMMIT();
    float* b2s = (float*)sm;
    float* w3s = (float*)(sm + 512);
    if (tid < 128){
        b2s[tid] = b2[(size_t)g * 512 + nc * 128 + tid];
        w3s[tid] = W3[(size_t)g * 512 + nc * 128 + tid];
    }
    CPWAIT0();
    __syncthreads();
    convW((const float*)(sm + K2_WF), sm + K2_B, nB, khB, ph);   // B0
    __syncthreads();

    float c[4][4][4];
#pragma unroll
    for (int i = 0; i < 4; i++)
#pragma unroll
    for (int jt = 0; jt < 4; jt++)
#pragma unroll
    for (int q = 0; q < 4; q++) c[i][jt][q] = 0.0f;
    Frag f = mk_frag(lane, wm, wn);

    for (int kt = 0; kt < 16; kt++){
        if (kt + 1 < 16){ cpA(kt + 1, (kt + 1) & 1); CPCOMMIT(); }
        if (kt + 2 < 16){ cpW(kt + 2, kt & 1); CPCOMMIT(); }
        // MMA first: tensor pipe starts immediately after the barrier
        mma32(sb + K2_A + (kt & 1) * 16384, sb + K2_B + (kt & 1) * 16384, f, c);
        if (kt + 1 < 16)
            convW((const float*)(sm + K2_WF + ((kt + 1) & 1) * 16384),
                  sm + K2_B + ((kt + 1) & 1) * 16384, nB, khB, ph);
        CPWAIT0();
        __syncthreads();
    }

    // epilogue: bias + gelu + W3-dot; quad shuffle + smem reduce
    float* red = (float*)(sm + 1024);
#pragma unroll
    for (int i = 0; i < 4; i++){
        float s0 = 0.0f, s1 = 0.0f;
#pragma unroll
        for (int jt = 0; jt < 4; jt++){
            int nl = wn * 32 + jt * 8 + 2 * (lane & 3);
            float bb0 = b2s[nl], bb1 = b2s[nl+1], ww0 = w3s[nl], ww1 = w3s[nl+1];
            s0 += gelu(c[i][jt][0] + bb0) * ww0 + gelu(c[i][jt][1] + bb1) * ww1;
            s1 += gelu(c[i][jt][2] + bb0) * ww0 + gelu(c[i][jt][3] + bb1) * ww1;
        }
        s0 += __shfl_xor_sync(0xFFFFFFFFu, s0, 1);
        s0 += __shfl_xor_sync(0xFFFFFFFFu, s0, 2);
        s1 += __shfl_xor_sync(0xFFFFFFFFu, s1, 1);
        s1 += __shfl_xor_sync(0xFFFFFFFFu, s1, 2);
        if ((lane & 3) == 0){
            int r0 = wm * 64 + i * 16 + (lane >> 2);
            red[r0 * 4 + wn] = s0;
            red[(r0 + 8) * 4 + wn] = s1;
        }
    }
    __syncthreads();
    if (tid < 128){
        const float* rr = red + tid * 4;
        g_part[((size_t)g * 4 + nc) * 128 + tid] = (rr[0] + rr[1]) + (rr[2] + rr[3]);
    }
}

// ============ k3 ============
__global__ void k3(const float* __restrict__ b3, float* __restrict__ out)
{
    int idx = blockIdx.x * 256 + threadIdx.x;
    if (idx >= 128 * NG) return;
    int m = idx / NG;
    int g = idx - m * NG;
    const float* p = g_part + (size_t)g * 512 + m;
    out[idx] = b3[g] + ((p[0] + p[128]) + (p[256] + p[384]));
}

extern "C" void kernel_launch(void* const* d_in, const int* in_sizes, int n_in,
                              void* d_out, int out_size)
{
    const float* x  = (const float*)d_in[0];
    const float* W1 = (const float*)d_in[1];
    const float* b1 = (const float*)d_in[2];
    const float* W2 = (const float*)d_in[3];
    const float* b2 = (const float*)d_in[4];
    const float* W3 = (const float*)d_in[5];
    const float* b3 = (const float*)d_in[6];
    float* out = (float*)d_out;

    cudaFuncSetAttribute(k1, cudaFuncAttributeMaxDynamicSharedMemorySize, SM1_BYTES);
    cudaFuncSetAttribute(k2, cudaFuncAttributeMaxDynamicSharedMemorySize, SM2_BYTES);

    k0<<<1, 256>>>(x);
    dim3 grid(4, NG);
    k1<<<grid, 256, SM1_BYTES>>>(W1, b1);
    k2<<<grid, 256, SM2_BYTES>>>(W2, b2, W3);
    k3<<<(128 * NG + 255) / 256, 256>>>(b3, out);
}